// round 6
// baseline (speedup 1.0000x reference)
#include <cuda_runtime.h>

// Problem constants: B=8, T=4096, C=32 (embedding), D=64 (head)
#define B_  8
#define T_  4096
#define C_  32
#define D_  64
#define NQT128 (T_ / 128)   // 32 query tiles (128 wide) per batch

typedef unsigned long long ull;

// smem layout (floats)
#define QP2   132                      // ys row stride (128 q + pad)
#define YS_OFF 0                       // ys[32][132]          = 4224
#define XT_STR (32 * 68)               // one xT buffer        = 2176
#define XT_OFF 4224                    // xT[2][32][68]        = 4352
#define XN_STR (64 * 36)               // one xN buffer        = 2304
#define XN_OFF (XT_OFF + 2 * XT_STR)   // xN[2][64][36]        = 4608
#define PS_OFF (XN_OFF + 2 * XN_STR)   // Ps[128][68]          = 8704
#define LV_OFF (PS_OFF + 128 * 68)     // linv[128]
#define SM_FLOATS (LV_OFF + 128)       // 22016 floats = 88064 B

// M = Wq * Wk^T  (32x32)
__device__ float g_M[C_ * C_];

// ---------------------------------------------------------------------------
// packed f32x2 helpers (sm_103a FFMA2 path)
// ---------------------------------------------------------------------------
__device__ __forceinline__ ull pack2(float a, float b) {
    ull r; asm("mov.b64 %0, {%1, %2};" : "=l"(r) : "f"(a), "f"(b)); return r;
}
__device__ __forceinline__ float2 unpack2(ull v) {
    float2 r; asm("mov.b64 {%0, %1}, %2;" : "=f"(r.x), "=f"(r.y) : "l"(v)); return r;
}
__device__ __forceinline__ void fma2(ull& d, ull a, ull b) {
    asm("fma.rn.f32x2 %0, %1, %2, %0;" : "+l"(d) : "l"(a), "l"(b));
}

// ---------------------------------------------------------------------------
// Kernel 0: M[i][j] = sum_d Wq[i][d] * Wk[j][d]
// ---------------------------------------------------------------------------
__global__ void m_kernel(const float* __restrict__ Wk, const float* __restrict__ Wq)
{
    const int i = threadIdx.x >> 5;
    const int j = threadIdx.x & 31;
    float s = 0.f;
    #pragma unroll
    for (int d = 0; d < D_; d++)
        s += Wq[i * D_ + d] * Wk[j * D_ + d];
    g_M[i * C_ + j] = s;
}

// ---------------------------------------------------------------------------
// Kernel 1: fused causal attention (M-trick, no-max softmax, prefetch).
// One CTA = (batch, 128-query tile). 256 threads. k-tiles of 64.
//   y = x_q * M;  S = y x_k^T (inner 32);  p = exp(S);  Z += p x_k;
//   out = (Z / l) * Wv.
// ---------------------------------------------------------------------------
__global__ __launch_bounds__(256, 2) void attn_kernel(
    const float* __restrict__ x, const float* __restrict__ Wv,
    float* __restrict__ out)
{
    extern __shared__ float smf[];
    float* ys  = smf + YS_OFF;
    float* xT0 = smf + XT_OFF;
    float* xN0 = smf + XN_OFF;
    float* Ps  = smf + PS_OFF;
    float* lv  = smf + LV_OFF;

    const int b   = blockIdx.y;
    const int qt  = (NQT128 - 1) - blockIdx.x;   // heaviest tiles first
    const int tid = threadIdx.x;
    const int tx  = tid & 15, ty = tid >> 4;     // S-pass: 16x16 grid, 8q x 4k
    const int zr  = tid >> 3;                    // Z-pass rows zr + 32*i
    const int zc  = (tid & 7) * 4;               // Z-pass cols zc..zc+3

    const float* xb   = x + b * T_ * C_;
    const int    ktmax = 2 * qt + 1;             // last 64-wide k tile

    // ---- stage x_q (128x32) into Ps ----
    {
        const float4* xq = (const float4*)(xb + qt * 128 * C_);
        #pragma unroll
        for (int it = 0; it < 4; it++) {
            int lin = tid + it * 256;            // 0..1023
            int r = lin >> 3, c4 = lin & 7;
            *(float4*)&Ps[r * 68 + c4 * 4] = xq[lin];
        }
    }
    __syncthreads();

    // ---- y = x_q * M -> ys (transposed [c'][q]) ----
    {
        const int c0 = tx * 2;
        float a0[8], a1[8];
        #pragma unroll
        for (int i = 0; i < 8; i++) { a0[i] = 0.f; a1[i] = 0.f; }
        #pragma unroll 8
        for (int c = 0; c < C_; c++) {
            float2 m2 = *(const float2*)&g_M[c * C_ + c0];
            #pragma unroll
            for (int i = 0; i < 8; i++) {
                float xv = Ps[(ty * 8 + i) * 68 + c];
                a0[i] += xv * m2.x;
                a1[i] += xv * m2.y;
            }
        }
        #pragma unroll
        for (int i = 0; i < 8; i++) {
            ys[(c0 + 0) * QP2 + ty * 8 + i] = a0[i];
            ys[(c0 + 1) * QP2 + ty * 8 + i] = a1[i];
        }
    }

    // ---- preload k-tile 0 into buffer 0 ----
    {
        const float4* xg = (const float4*)xb;
        float4 p0 = xg[tid], p1 = xg[tid + 256];
        int r = tid >> 3, c4 = tid & 7;
        *(float4*)&xN0[r * 36 + c4 * 4] = p0;
        xT0[(c4 * 4 + 0) * 68 + r] = p0.x;
        xT0[(c4 * 4 + 1) * 68 + r] = p0.y;
        xT0[(c4 * 4 + 2) * 68 + r] = p0.z;
        xT0[(c4 * 4 + 3) * 68 + r] = p0.w;
        int r2 = r + 32;
        *(float4*)&xN0[r2 * 36 + c4 * 4] = p1;
        xT0[(c4 * 4 + 0) * 68 + r2] = p1.x;
        xT0[(c4 * 4 + 1) * 68 + r2] = p1.y;
        xT0[(c4 * 4 + 2) * 68 + r2] = p1.z;
        xT0[(c4 * 4 + 3) * 68 + r2] = p1.w;
    }

    float l_i[8];
    #pragma unroll
    for (int i = 0; i < 8; i++) l_i[i] = 0.f;
    ull z2[4][2];
    #pragma unroll
    for (int i = 0; i < 4; i++) { z2[i][0] = 0ull; z2[i][1] = 0ull; }

    for (int kt = 0; kt <= ktmax; kt++) {
        const int buf = kt & 1;
        const float* xTb = xT0 + buf * XT_STR;
        const float* xNb = xN0 + buf * XN_STR;

        __syncthreads();   // (A) this buf's load complete; prior Z-pass done

        // issue prefetch of next k-tile (latency hidden behind S-pass)
        float4 p0, p1;
        const bool pf = (kt < ktmax);
        if (pf) {
            const float4* xg = (const float4*)(xb + (kt + 1) * 64 * C_);
            p0 = xg[tid]; p1 = xg[tid + 256];
        }

        // ---- S = y * x_k^T : 8q x 4k per thread, q-paired FFMA2 ----
        ull s2[4][4];
        #pragma unroll
        for (int j = 0; j < 4; j++)
            #pragma unroll
            for (int i2 = 0; i2 < 4; i2++) s2[j][i2] = 0ull;

        #pragma unroll 8
        for (int c = 0; c < C_; c++) {
            float4 qa = *(const float4*)&ys[c * QP2 + ty * 8];
            float4 qb = *(const float4*)&ys[c * QP2 + ty * 8 + 4];
            float4 kv = *(const float4*)&xTb[c * 68 + tx * 4];
            ull qp[4] = { pack2(qa.x, qa.y), pack2(qa.z, qa.w),
                          pack2(qb.x, qb.y), pack2(qb.z, qb.w) };
            ull kd[4] = { pack2(kv.x, kv.x), pack2(kv.y, kv.y),
                          pack2(kv.z, kv.z), pack2(kv.w, kv.w) };
            #pragma unroll
            for (int j = 0; j < 4; j++)
                #pragma unroll
                for (int i2 = 0; i2 < 4; i2++)
                    fma2(s2[j][i2], qp[i2], kd[j]);
        }

        float s[8][4];
        #pragma unroll
        for (int j = 0; j < 4; j++)
            #pragma unroll
            for (int i2 = 0; i2 < 4; i2++) {
                float2 u = unpack2(s2[j][i2]);
                s[2 * i2 + 0][j] = u.x;
                s[2 * i2 + 1][j] = u.y;
            }

        if (kt >= 2 * qt) {   // causal mask (only last two k tiles)
            const int koff = (kt - 2 * qt) * 64;
            #pragma unroll
            for (int i = 0; i < 8; i++)
                #pragma unroll
                for (int j = 0; j < 4; j++)
                    if (koff + tx * 4 + j > ty * 8 + i) s[i][j] = -1e30f;
        }

        // ---- store prefetched tile into other buffer ----
        if (pf) {
            const int nb = buf ^ 1;
            float* xNn = xN0 + nb * XN_STR;
            float* xTn = xT0 + nb * XT_STR;
            int r = tid >> 3, c4 = tid & 7;
            *(float4*)&xNn[r * 36 + c4 * 4] = p0;
            xTn[(c4 * 4 + 0) * 68 + r] = p0.x;
            xTn[(c4 * 4 + 1) * 68 + r] = p0.y;
            xTn[(c4 * 4 + 2) * 68 + r] = p0.z;
            xTn[(c4 * 4 + 3) * 68 + r] = p0.w;
            int r2 = r + 32;
            *(float4*)&xNn[r2 * 36 + c4 * 4] = p1;
            xTn[(c4 * 4 + 0) * 68 + r2] = p1.x;
            xTn[(c4 * 4 + 1) * 68 + r2] = p1.y;
            xTn[(c4 * 4 + 2) * 68 + r2] = p1.z;
            xTn[(c4 * 4 + 3) * 68 + r2] = p1.w;
        }

        // ---- softmax-lite: p = exp(s), local row-sum only ----
        #pragma unroll
        for (int i = 0; i < 8; i++) {
            float e0 = __expf(s[i][0]);
            float e1 = __expf(s[i][1]);
            float e2 = __expf(s[i][2]);
            float e3 = __expf(s[i][3]);
            l_i[i] += (e0 + e1) + (e2 + e3);
            *(float4*)&Ps[(ty * 8 + i) * 68 + tx * 4] = make_float4(e0, e1, e2, e3);
        }
        __syncthreads();   // (B) Ps visible

        // ---- Z += P * x_k : rows zr+32i, cols zc..zc+3, c-paired FFMA2 ----
        #pragma unroll 4
        for (int k4 = 0; k4 < 16; k4++) {
            float4 xv[4], pr[4];
            #pragma unroll
            for (int kk = 0; kk < 4; kk++)
                xv[kk] = *(const float4*)&xNb[(k4 * 4 + kk) * 36 + zc];
            #pragma unroll
            for (int i = 0; i < 4; i++)
                pr[i] = *(const float4*)&Ps[(zr + 32 * i) * 68 + k4 * 4];

            ull xlo[4], xhi[4];
            #pragma unroll
            for (int kk = 0; kk < 4; kk++) {
                xlo[kk] = pack2(xv[kk].x, xv[kk].y);
                xhi[kk] = pack2(xv[kk].z, xv[kk].w);
            }
            #pragma unroll
            for (int i = 0; i < 4; i++) {
                const float* pv = (const float*)&pr[i];
                #pragma unroll
                for (int kk = 0; kk < 4; kk++) {
                    ull pd = pack2(pv[kk], pv[kk]);
                    fma2(z2[i][0], pd, xlo[kk]);
                    fma2(z2[i][1], pd, xhi[kk]);
                }
            }
        }
    }

    // ---- reduce row sums l across 16 tx lanes (once, at the end) ----
    #pragma unroll
    for (int i = 0; i < 8; i++) {
        float rs = l_i[i];
        rs += __shfl_xor_sync(0xffffffffu, rs, 8);
        rs += __shfl_xor_sync(0xffffffffu, rs, 4);
        rs += __shfl_xor_sync(0xffffffffu, rs, 2);
        rs += __shfl_xor_sync(0xffffffffu, rs, 1);
        if (tx == 0) lv[ty * 8 + i] = 1.f / rs;
    }
    __syncthreads();   // Z-pass reads of Ps done; lv visible

    // ---- scale Z by 1/l, stage into Ps ----
    #pragma unroll
    for (int i = 0; i < 4; i++) {
        float li = lv[zr + 32 * i];
        float2 a = unpack2(z2[i][0]);
        float2 c = unpack2(z2[i][1]);
        *(float4*)&Ps[(zr + 32 * i) * 68 + zc] =
            make_float4(a.x * li, a.y * li, c.x * li, c.y * li);
    }
    {   // load Wv [32][64] into xT buffer 0
        const float4* wg = (const float4*)Wv;
        #pragma unroll
        for (int it = 0; it < 2; it++) {
            int lin = tid + it * 256;           // 0..511
            int r = lin >> 4, c4 = lin & 15;
            *(float4*)&xT0[r * 68 + c4 * 4] = wg[lin];
        }
    }
    __syncthreads();

    // ---- out = (Z/l) * Wv : 8q x 4d per thread ----
    float o[8][4];
    #pragma unroll
    for (int i = 0; i < 8; i++)
        #pragma unroll
        for (int j = 0; j < 4; j++) o[i][j] = 0.f;

    #pragma unroll 4
    for (int c = 0; c < C_; c++) {
        float4 w4 = *(const float4*)&xT0[c * 68 + tx * 4];
        #pragma unroll
        for (int i = 0; i < 8; i++) {
            float zv = Ps[(ty * 8 + i) * 68 + c];
            o[i][0] += zv * w4.x; o[i][1] += zv * w4.y;
            o[i][2] += zv * w4.z; o[i][3] += zv * w4.w;
        }
    }

    float* Og = out + (b * T_ + qt * 128) * D_;
    #pragma unroll
    for (int i = 0; i < 8; i++)
        *(float4*)&Og[(ty * 8 + i) * D_ + tx * 4] =
            make_float4(o[i][0], o[i][1], o[i][2], o[i][3]);
}

// ---------------------------------------------------------------------------
extern "C" void kernel_launch(void* const* d_in, const int* in_sizes, int n_in,
                              void* d_out, int out_size)
{
    const float* x  = (const float*)d_in[0];
    const float* Wk = (const float*)d_in[1];
    const float* Wq = (const float*)d_in[2];
    const float* Wv = (const float*)d_in[3];
    float* out = (float*)d_out;

    m_kernel<<<1, 1024>>>(Wk, Wq);

    const int smem = SM_FLOATS * (int)sizeof(float);   // 88064 B
    cudaFuncSetAttribute(attn_kernel, cudaFuncAttributeMaxDynamicSharedMemorySize, smem);
    attn_kernel<<<dim3(NQT128, B_), 256, smem>>>(x, Wv, out);
}

// round 7
// speedup vs baseline: 1.7933x; 1.7933x over previous
#include <cuda_runtime.h>

// Problem constants: B=8, T=4096, C=32 (embedding), D=64 (head)
#define B_  8
#define T_  4096
#define C_  32
#define D_  64
#define NQT128 32            // 128-wide query tiles per batch
#define NCHUNK 8             // k-chunks per query tile (each <=8 k-passes of 64)

typedef unsigned long long ull;

// smem layout for attn kernel (floats)
#define QP2   132                      // ys row stride (128 q + pad)
#define YS_OFF 0                       // ys[32][132]
#define XT_STR (32 * 68)
#define XT_OFF 4224                    // xT[2][32][68]
#define XN_STR (64 * 36)
#define XN_OFF (XT_OFF + 2 * XT_STR)   // xN[2][64][36]
#define PS_OFF (XN_OFF + 2 * XN_STR)   // Ps[128][68]
#define SM_FLOATS (PS_OFF + 128 * 68)  // 21888 floats = 87552 B

// M = Wq * Wk^T  (32x32)
__device__ float g_M[C_ * C_];
// split-K partials: slot = ((b*32+qt)*8 + chunk)
__device__ float g_partZ[B_ * NQT128 * NCHUNK * 128 * 32];   // 33.5 MB
__device__ float g_partL[B_ * NQT128 * NCHUNK * 128];

// ---------------------------------------------------------------------------
// packed f32x2 helpers (sm_103a FFMA2 path)
// ---------------------------------------------------------------------------
__device__ __forceinline__ ull pack2(float a, float b) {
    ull r; asm("mov.b64 %0, {%1, %2};" : "=l"(r) : "f"(a), "f"(b)); return r;
}
__device__ __forceinline__ float2 unpack2(ull v) {
    float2 r; asm("mov.b64 {%0, %1}, %2;" : "=f"(r.x), "=f"(r.y) : "l"(v)); return r;
}
__device__ __forceinline__ void fma2(ull& d, ull a, ull b) {
    asm("fma.rn.f32x2 %0, %1, %2, %0;" : "+l"(d) : "l"(a), "l"(b));
}

// ---------------------------------------------------------------------------
// Kernel 0: M[i][j] = sum_d Wq[i][d] * Wk[j][d]
// ---------------------------------------------------------------------------
__global__ void m_kernel(const float* __restrict__ Wk, const float* __restrict__ Wq)
{
    const int i = threadIdx.x >> 5;
    const int j = threadIdx.x & 31;
    float s = 0.f;
    #pragma unroll
    for (int d = 0; d < D_; d++)
        s += Wq[i * D_ + d] * Wk[j * D_ + d];
    g_M[i * C_ + j] = s;
}

// ---------------------------------------------------------------------------
// Kernel 1: split-K attention partials.
// One CTA = (b, qt, chunk): k-tiles [8*chunk, min(2qt+2, 8*chunk+8)).
//   y = x_q*M;  S = y x_k^T;  p = exp(S);  Zpart += p x_k;  lpart += rowsum(p)
// ---------------------------------------------------------------------------
__global__ __launch_bounds__(256, 2) void attn_kernel(const float* __restrict__ x)
{
    const int b     = blockIdx.y;
    const int qt    = (NQT128 - 1) - (blockIdx.x >> 3);  // heaviest first
    const int chunk = blockIdx.x & 7;
    const int k0    = chunk * 8;
    const int k1e   = 2 * qt + 2;                        // one past last k-tile
    if (k0 >= k1e) return;                               // empty chunk
    const int k1    = (k1e < k0 + 8) ? k1e : (k0 + 8);

    extern __shared__ float smf[];
    float* ys  = smf + YS_OFF;
    float* xT0 = smf + XT_OFF;
    float* xN0 = smf + XN_OFF;
    float* Ps  = smf + PS_OFF;

    const int tid = threadIdx.x;
    const int tx  = tid & 15, ty = tid >> 4;   // S-pass: 8q x 4k per thread
    const int zr  = tid >> 3;                  // Z-pass rows zr + 32*i
    const int zc  = (tid & 7) * 4;             // Z-pass cols zc..zc+3

    const float* xb = x + b * T_ * C_;

    // ---- stage x_q (128x32) into Ps ----
    {
        const float4* xq = (const float4*)(xb + qt * 128 * C_);
        #pragma unroll
        for (int it = 0; it < 4; it++) {
            int lin = tid + it * 256;
            int r = lin >> 3, c4 = lin & 7;
            *(float4*)&Ps[r * 68 + c4 * 4] = xq[lin];
        }
    }
    __syncthreads();

    // ---- y = x_q * M -> ys (transposed [c'][q]) ----
    {
        const int c0 = tx * 2;
        float a0[8], a1[8];
        #pragma unroll
        for (int i = 0; i < 8; i++) { a0[i] = 0.f; a1[i] = 0.f; }
        #pragma unroll 8
        for (int c = 0; c < C_; c++) {
            float2 m2 = *(const float2*)&g_M[c * C_ + c0];
            #pragma unroll
            for (int i = 0; i < 8; i++) {
                float xv = Ps[(ty * 8 + i) * 68 + c];
                a0[i] += xv * m2.x;
                a1[i] += xv * m2.y;
            }
        }
        #pragma unroll
        for (int i = 0; i < 8; i++) {
            ys[(c0 + 0) * QP2 + ty * 8 + i] = a0[i];
            ys[(c0 + 1) * QP2 + ty * 8 + i] = a1[i];
        }
    }

    // ---- preload k-tile k0 into buffer 0 ----
    {
        const float4* xg = (const float4*)(xb + k0 * 64 * C_);
        float4 p0 = xg[tid], p1 = xg[tid + 256];
        int r = tid >> 3, c4 = tid & 7;
        *(float4*)&xN0[r * 36 + c4 * 4] = p0;
        xT0[(c4 * 4 + 0) * 68 + r] = p0.x;
        xT0[(c4 * 4 + 1) * 68 + r] = p0.y;
        xT0[(c4 * 4 + 2) * 68 + r] = p0.z;
        xT0[(c4 * 4 + 3) * 68 + r] = p0.w;
        int r2 = r + 32;
        *(float4*)&xN0[r2 * 36 + c4 * 4] = p1;
        xT0[(c4 * 4 + 0) * 68 + r2] = p1.x;
        xT0[(c4 * 4 + 1) * 68 + r2] = p1.y;
        xT0[(c4 * 4 + 2) * 68 + r2] = p1.z;
        xT0[(c4 * 4 + 3) * 68 + r2] = p1.w;
    }

    float l_i[8];
    #pragma unroll
    for (int i = 0; i < 8; i++) l_i[i] = 0.f;
    ull z2[4][2];
    #pragma unroll
    for (int i = 0; i < 4; i++) { z2[i][0] = 0ull; z2[i][1] = 0ull; }

    for (int kt = k0; kt < k1; kt++) {
        const int buf = (kt - k0) & 1;
        const float* xTb = xT0 + buf * XT_STR;
        const float* xNb = xN0 + buf * XN_STR;

        __syncthreads();   // (A) this buf loaded; prior Z-pass done

        // prefetch next k-tile (registers; stored after S-pass)
        float4 p0, p1;
        const bool pf = (kt + 1 < k1);
        if (pf) {
            const float4* xg = (const float4*)(xb + (kt + 1) * 64 * C_);
            p0 = xg[tid]; p1 = xg[tid + 256];
        }

        // ---- S = y * x_k^T : 8q x 4k per thread, q-paired FFMA2 ----
        ull s2[4][4];
        #pragma unroll
        for (int j = 0; j < 4; j++)
            #pragma unroll
            for (int i2 = 0; i2 < 4; i2++) s2[j][i2] = 0ull;

        #pragma unroll 8
        for (int c = 0; c < C_; c++) {
            float4 qa = *(const float4*)&ys[c * QP2 + ty * 8];
            float4 qb = *(const float4*)&ys[c * QP2 + ty * 8 + 4];
            float4 kv = *(const float4*)&xTb[c * 68 + tx * 4];
            ull qp[4] = { pack2(qa.x, qa.y), pack2(qa.z, qa.w),
                          pack2(qb.x, qb.y), pack2(qb.z, qb.w) };
            ull kd[4] = { pack2(kv.x, kv.x), pack2(kv.y, kv.y),
                          pack2(kv.z, kv.z), pack2(kv.w, kv.w) };
            #pragma unroll
            for (int j = 0; j < 4; j++)
                #pragma unroll
                for (int i2 = 0; i2 < 4; i2++)
                    fma2(s2[j][i2], qp[i2], kd[j]);
        }

        float s[8][4];
        #pragma unroll
        for (int j = 0; j < 4; j++)
            #pragma unroll
            for (int i2 = 0; i2 < 4; i2++) {
                float2 u = unpack2(s2[j][i2]);
                s[2 * i2 + 0][j] = u.x;
                s[2 * i2 + 1][j] = u.y;
            }

        if (kt >= 2 * qt) {   // causal mask (last two k-tiles of this qt)
            const int koff = (kt - 2 * qt) * 64;
            #pragma unroll
            for (int i = 0; i < 8; i++)
                #pragma unroll
                for (int j = 0; j < 4; j++)
                    if (koff + tx * 4 + j > ty * 8 + i) s[i][j] = -1e30f;
        }

        // ---- store prefetched tile into other buffer ----
        if (pf) {
            const int nb = buf ^ 1;
            float* xNn = xN0 + nb * XN_STR;
            float* xTn = xT0 + nb * XT_STR;
            int r = tid >> 3, c4 = tid & 7;
            *(float4*)&xNn[r * 36 + c4 * 4] = p0;
            xTn[(c4 * 4 + 0) * 68 + r] = p0.x;
            xTn[(c4 * 4 + 1) * 68 + r] = p0.y;
            xTn[(c4 * 4 + 2) * 68 + r] = p0.z;
            xTn[(c4 * 4 + 3) * 68 + r] = p0.w;
            int r2 = r + 32;
            *(float4*)&xNn[r2 * 36 + c4 * 4] = p1;
            xTn[(c4 * 4 + 0) * 68 + r2] = p1.x;
            xTn[(c4 * 4 + 1) * 68 + r2] = p1.y;
            xTn[(c4 * 4 + 2) * 68 + r2] = p1.z;
            xTn[(c4 * 4 + 3) * 68 + r2] = p1.w;
        }

        // ---- p = exp(s), accumulate local row-sum ----
        #pragma unroll
        for (int i = 0; i < 8; i++) {
            float e0 = __expf(s[i][0]);
            float e1 = __expf(s[i][1]);
            float e2 = __expf(s[i][2]);
            float e3 = __expf(s[i][3]);
            l_i[i] += (e0 + e1) + (e2 + e3);
            *(float4*)&Ps[(ty * 8 + i) * 68 + tx * 4] = make_float4(e0, e1, e2, e3);
        }
        __syncthreads();   // (B) Ps visible

        // ---- Z += P * x_k : rows zr+32i, cols zc..zc+3, c-paired FFMA2 ----
        #pragma unroll 4
        for (int k4 = 0; k4 < 16; k4++) {
            float4 xv[4], pr[4];
            #pragma unroll
            for (int kk = 0; kk < 4; kk++)
                xv[kk] = *(const float4*)&xNb[(k4 * 4 + kk) * 36 + zc];
            #pragma unroll
            for (int i = 0; i < 4; i++)
                pr[i] = *(const float4*)&Ps[(zr + 32 * i) * 68 + k4 * 4];

            ull xlo[4], xhi[4];
            #pragma unroll
            for (int kk = 0; kk < 4; kk++) {
                xlo[kk] = pack2(xv[kk].x, xv[kk].y);
                xhi[kk] = pack2(xv[kk].z, xv[kk].w);
            }
            #pragma unroll
            for (int i = 0; i < 4; i++) {
                const float* pv = (const float*)&pr[i];
                #pragma unroll
                for (int kk = 0; kk < 4; kk++) {
                    ull pd = pack2(pv[kk], pv[kk]);
                    fma2(z2[i][0], pd, xlo[kk]);
                    fma2(z2[i][1], pd, xhi[kk]);
                }
            }
        }
    }

    // ---- write partials ----
    const int islot = (b * NQT128 + qt) * NCHUNK + chunk;

    #pragma unroll
    for (int i = 0; i < 8; i++) {   // partial row sums (raw, reduced over tx)
        float rs = l_i[i];
        rs += __shfl_xor_sync(0xffffffffu, rs, 8);
        rs += __shfl_xor_sync(0xffffffffu, rs, 4);
        rs += __shfl_xor_sync(0xffffffffu, rs, 2);
        rs += __shfl_xor_sync(0xffffffffu, rs, 1);
        if (tx == 0) g_partL[islot * 128 + ty * 8 + i] = rs;
    }

    float* zp = g_partZ + islot * (128 * 32);
    #pragma unroll
    for (int i = 0; i < 4; i++) {
        float2 a = unpack2(z2[i][0]);
        float2 c = unpack2(z2[i][1]);
        *(float4*)&zp[(zr + 32 * i) * 32 + zc] = make_float4(a.x, a.y, c.x, c.y);
    }
}

// ---------------------------------------------------------------------------
// Kernel 2: reduce partials, out = (Z / l) * Wv.  One CTA = (b, qt).
// ---------------------------------------------------------------------------
__global__ __launch_bounds__(256) void reduce_kernel(
    const float* __restrict__ Wv, float* __restrict__ out)
{
    __shared__ float Zs[128][36];
    __shared__ float Wvs[32][68];
    __shared__ float lv[128];

    const int qt  = blockIdx.x;
    const int b   = blockIdx.y;
    const int tid = threadIdx.x;
    const int nc  = (2 * qt + 1) / 8 + 1;   // valid chunks for this qt
    const int base = (b * NQT128 + qt) * NCHUNK;

    // sum partial Z (each thread owns 4 float4 across the 128x32 tile)
    float4 acc[4];
    #pragma unroll
    for (int it = 0; it < 4; it++) acc[it] = make_float4(0.f, 0.f, 0.f, 0.f);
    for (int s = 0; s < nc; s++) {
        const float4* zp = (const float4*)(g_partZ + (base + s) * (128 * 32));
        #pragma unroll
        for (int it = 0; it < 4; it++) {
            float4 v = zp[tid + it * 256];
            acc[it].x += v.x; acc[it].y += v.y; acc[it].z += v.z; acc[it].w += v.w;
        }
    }
    // sum partial l
    if (tid < 128) {
        float ls = 0.f;
        for (int s = 0; s < nc; s++)
            ls += g_partL[(base + s) * 128 + tid];
        lv[tid] = 1.f / ls;
    }
    __syncthreads();

    // stage Z scaled by 1/l
    #pragma unroll
    for (int it = 0; it < 4; it++) {
        int lin = tid + it * 256;
        int r = lin >> 3, c4 = lin & 7;
        float li = lv[r];
        *(float4*)&Zs[r][c4 * 4] = make_float4(acc[it].x * li, acc[it].y * li,
                                               acc[it].z * li, acc[it].w * li);
    }
    // load Wv [32][64]
    {
        const float4* wg = (const float4*)Wv;
        #pragma unroll
        for (int it = 0; it < 2; it++) {
            int lin = tid + it * 256;
            int r = lin >> 4, c4 = lin & 15;
            *(float4*)&Wvs[r][c4 * 4] = wg[lin];
        }
    }
    __syncthreads();

    // out = Z * Wv : rows ty + 16*i (2-way broadcast smem reads), cols tx*4..+3
    const int tx = tid & 15, ty = tid >> 4;
    float o[8][4];
    #pragma unroll
    for (int i = 0; i < 8; i++)
        #pragma unroll
        for (int j = 0; j < 4; j++) o[i][j] = 0.f;

    #pragma unroll 4
    for (int c = 0; c < C_; c++) {
        float4 w4 = *(const float4*)&Wvs[c][tx * 4];
        #pragma unroll
        for (int i = 0; i < 8; i++) {
            float zv = Zs[ty + 16 * i][c];
            o[i][0] += zv * w4.x; o[i][1] += zv * w4.y;
            o[i][2] += zv * w4.z; o[i][3] += zv * w4.w;
        }
    }

    float* Og = out + (b * T_ + qt * 128) * D_;
    #pragma unroll
    for (int i = 0; i < 8; i++)
        *(float4*)&Og[(ty + 16 * i) * D_ + tx * 4] =
            make_float4(o[i][0], o[i][1], o[i][2], o[i][3]);
}

// ---------------------------------------------------------------------------
extern "C" void kernel_launch(void* const* d_in, const int* in_sizes, int n_in,
                              void* d_out, int out_size)
{
    const float* x  = (const float*)d_in[0];
    const float* Wk = (const float*)d_in[1];
    const float* Wq = (const float*)d_in[2];
    const float* Wv = (const float*)d_in[3];
    float* out = (float*)d_out;

    m_kernel<<<1, 1024>>>(Wk, Wq);

    const int smem = SM_FLOATS * (int)sizeof(float);   // 87552 B
    cudaFuncSetAttribute(attn_kernel, cudaFuncAttributeMaxDynamicSharedMemorySize, smem);
    attn_kernel<<<dim3(NQT128 * NCHUNK, B_), 256, smem>>>(x);

    reduce_kernel<<<dim3(NQT128, B_), 256>>>(Wv, out);
}